// round 14
// baseline (speedup 1.0000x reference)
#include <cuda_runtime.h>
#include <cuda_bf16.h>
#include <math.h>
#include <stdint.h>

// Problem constants (fixed by the dataset)
#define BB   2
#define DD   256
#define THW  8192
#define NN   16384
#define KK   8192

#define MARGIN 0.30f
#define CAP    1024

// -------- device scratch (no allocations allowed) --------
__device__ float g_H1[KK * DD];
__device__ float g_CB[KK * DD];
__device__ signed char g_CBq[KK * DD];
__device__ signed char g_Zq[NN * DD];
__device__ __nv_bfloat16 g_Zhi[NN * DD];
__device__ __nv_bfloat16 g_Zlo[NN * DD];
__device__ float g_cbsq[KK];
__device__ float g_cf[KK];            // per-code -2*s_z*s_c
__device__ unsigned g_cmaxb[KK];      // per-code max|c| (float bits)
__device__ unsigned g_maxzb;          // global max|z| (float bits)
__device__ float g_csum[DD];
__device__ float g_zcol[DD];
__device__ float g_scal[3];
__device__ unsigned long long g_best[NN];
__device__ int   g_counts[KK];
__device__ int   g_ccount[NN];
__device__ unsigned short g_cand[(size_t)NN * CAP];   // 32 MB

// ================= PTX helpers (base sm_103-safe) =====
__device__ __forceinline__ uint32_t smem_to_u32(const void* p) {
    uint32_t a;
    asm("{ .reg .u64 t; cvta.to.shared.u64 t, %1; cvt.u32.u64 %0, t; }" : "=r"(a) : "l"(p));
    return a;
}
__device__ __forceinline__ void cpa16(uint32_t saddr, const void* g) {
    asm volatile("cp.async.cg.shared.global [%0], [%1], 16;" :: "r"(saddr), "l"(g) : "memory");
}
#define CP_COMMIT() asm volatile("cp.async.commit_group;" ::: "memory")
#define CP_WAIT1()  asm volatile("cp.async.wait_group 1;" ::: "memory")

__device__ __forceinline__ void ldsm4(uint32_t (&r)[4], uint32_t addr) {
    asm volatile("ldmatrix.sync.aligned.m8n8.x4.shared.b16 {%0,%1,%2,%3}, [%4];"
        : "=r"(r[0]), "=r"(r[1]), "=r"(r[2]), "=r"(r[3]) : "r"(addr));
}
__device__ __forceinline__ void mma_s8(int (&d)[4], const uint32_t (&a)[4],
                                       uint32_t b0, uint32_t b1) {
    asm volatile("mma.sync.aligned.m16n8k32.row.col.s32.s8.s8.s32 "
        "{%0,%1,%2,%3}, {%4,%5,%6,%7}, {%8,%9}, {%0,%1,%2,%3};"
        : "+r"(d[0]), "+r"(d[1]), "+r"(d[2]), "+r"(d[3])
        : "r"(a[0]), "r"(a[1]), "r"(a[2]), "r"(a[3]), "r"(b0), "r"(b1));
}

// -------- helpers --------
__device__ __forceinline__ float blockReduceSum(float v) {
    __shared__ float sh[32];
    int lane = threadIdx.x & 31, w = threadIdx.x >> 5;
    #pragma unroll
    for (int o = 16; o; o >>= 1) v += __shfl_xor_sync(0xffffffffu, v, o);
    if (lane == 0) sh[w] = v;
    __syncthreads();
    v = (threadIdx.x < (blockDim.x >> 5)) ? sh[threadIdx.x] : 0.f;
    if (w == 0) {
        #pragma unroll
        for (int o = 16; o; o >>= 1) v += __shfl_xor_sync(0xffffffffu, v, o);
    }
    __syncthreads();
    return v;
}

__global__ void k_init() {
    int t = blockIdx.x * blockDim.x + threadIdx.x;
    if (t < NN) { g_best[t] = ~0ull; g_ccount[t] = 0; }
    if (t < KK) { g_counts[t] = 0; g_cbsq[t] = 0.f; g_cmaxb[t] = 0u; }
    if (t < DD) { g_csum[t] = 0.f; g_zcol[t] = 0.f; }
    if (t < 3)  g_scal[t] = 0.f;
    if (t == 0) g_maxzb = 0u;
}

// ======== fused: gemm0 (H1 = gelu(emb @ w1^T)) [z==0] + zsplit [z==1] ========
__global__ void __launch_bounds__(256) fused_pre(const float* __restrict__ z,
                                                 const float* __restrict__ emb,
                                                 const float* __restrict__ w1) {
    __shared__ __align__(16) float sh[8384];
    int tid = threadIdx.x;

    if (blockIdx.z == 0) {
        float (*As)[64] = (float (*)[64])sh;
        float (*Bs)[64] = (float (*)[64])(sh + 1024);
        int m0 = blockIdx.y * 64, n0 = blockIdx.x * 64;
        int ty = tid >> 4, tx = tid & 15;
        int lr = tid >> 2, lseg = tid & 3;
        float acc[4][4];
        #pragma unroll
        for (int i = 0; i < 4; i++)
            #pragma unroll
            for (int j = 0; j < 4; j++) acc[i][j] = 0.f;
        for (int d0 = 0; d0 < 256; d0 += 16) {
            __syncthreads();
            float4 va = *(const float4*)(emb + (size_t)(m0 + lr) * 256 + d0 + lseg * 4);
            As[lseg * 4 + 0][lr] = va.x; As[lseg * 4 + 1][lr] = va.y;
            As[lseg * 4 + 2][lr] = va.z; As[lseg * 4 + 3][lr] = va.w;
            float4 vb = *(const float4*)(w1 + (size_t)(n0 + lr) * 256 + d0 + lseg * 4);
            Bs[lseg * 4 + 0][lr] = vb.x; Bs[lseg * 4 + 1][lr] = vb.y;
            Bs[lseg * 4 + 2][lr] = vb.z; Bs[lseg * 4 + 3][lr] = vb.w;
            __syncthreads();
            #pragma unroll
            for (int kk = 0; kk < 16; kk++) {
                float4 a = *(float4*)&As[kk][ty * 4];
                float4 b = *(float4*)&Bs[kk][tx * 4];
                float ar[4] = {a.x, a.y, a.z, a.w};
                float br[4] = {b.x, b.y, b.z, b.w};
                #pragma unroll
                for (int i = 0; i < 4; i++)
                    #pragma unroll
                    for (int j = 0; j < 4; j++) acc[i][j] += ar[i] * br[j];
            }
        }
        #pragma unroll
        for (int i = 0; i < 4; i++)
            #pragma unroll
            for (int j = 0; j < 4; j++) {
                float x = acc[i][j];
                g_H1[(size_t)(m0 + ty * 4 + i) * 256 + n0 + tx * 4 + j] =
                    0.5f * x * (1.f + erff(x * 0.70710678118654752f));
            }
        return;
    }

    // ---------------- zsplit: transpose + bf16 split + stats + |z|max -------
    float (*sm)[261] = (float (*)[261])sh;
    float* zc = sh + 8352;
    int idx = blockIdx.y * 4 + blockIdx.x;
    int s0 = (idx & 31) * 256, d0 = ((idx >> 5) & 7) * 32, b = idx >> 8;
    if (tid < 32) zc[tid] = 0.f;
    const float* zp = z + ((size_t)b * 256 + d0) * THW + s0;
    #pragma unroll
    for (int i = 0; i < 32; i++) sm[i][tid] = zp[(size_t)i * THW + tid];
    __syncthreads();
    {
        int i = tid & 31, c = tid >> 5;
        float s = 0.f, s2 = 0.f, am = 0.f;
        #pragma unroll
        for (int u = 0; u < 32; u++) {
            float v = sm[i][c * 32 + u];
            s += v; s2 += v * v;
            am = fmaxf(am, fabsf(v));
        }
        atomicAdd(&zc[i], s);
        #pragma unroll
        for (int o = 16; o; o >>= 1) am = fmaxf(am, __shfl_xor_sync(0xffffffffu, am, o));
        if ((tid & 31) == 0) atomicMax(&g_maxzb, __float_as_uint(am));
        float ts2 = blockReduceSum(s2);
        if (tid == 0) atomicAdd(&g_scal[0], ts2);
    }
    int dseg = tid & 7, sl = tid >> 3;
    #pragma unroll
    for (int w = 0; w < 8; w++) {
        int s_i = w * 32 + sl;
        float x0 = sm[dseg * 4 + 0][s_i];
        float x1 = sm[dseg * 4 + 1][s_i];
        float x2 = sm[dseg * 4 + 2][s_i];
        float x3 = sm[dseg * 4 + 3][s_i];
        __nv_bfloat16 h0 = __float2bfloat16_rn(x0), h1 = __float2bfloat16_rn(x1);
        __nv_bfloat16 h2 = __float2bfloat16_rn(x2), h3 = __float2bfloat16_rn(x3);
        __nv_bfloat162 hp0 = __halves2bfloat162(h0, h1);
        __nv_bfloat162 hp1 = __halves2bfloat162(h2, h3);
        __nv_bfloat16 l0 = __float2bfloat16_rn(x0 - __bfloat162float(h0));
        __nv_bfloat16 l1 = __float2bfloat16_rn(x1 - __bfloat162float(h1));
        __nv_bfloat16 l2 = __float2bfloat16_rn(x2 - __bfloat162float(h2));
        __nv_bfloat16 l3 = __float2bfloat16_rn(x3 - __bfloat162float(h3));
        __nv_bfloat162 lp0 = __halves2bfloat162(l0, l1);
        __nv_bfloat162 lp1 = __halves2bfloat162(l2, l3);
        size_t base = ((size_t)(b * THW + s0 + s_i) * 256) + d0 + dseg * 4;
        *(uint2*)(g_Zhi + base) = make_uint2(*reinterpret_cast<uint32_t*>(&hp0),
                                             *reinterpret_cast<uint32_t*>(&hp1));
        *(uint2*)(g_Zlo + base) = make_uint2(*reinterpret_cast<uint32_t*>(&lp0),
                                             *reinterpret_cast<uint32_t*>(&lp1));
    }
    __syncthreads();
    if (tid < 32) atomicAdd(&g_zcol[d0 + tid], zc[tid]);
}

// -------- gemm1: CB = H1 @ w2^T, fused stats + per-row max epilogue --------
__global__ void __launch_bounds__(256) gemm_cb(const float* __restrict__ Bm) {
    __shared__ __align__(16) float As[16][64];
    __shared__ __align__(16) float Bs[16][64];
    __shared__ float colsum[64];
    int m0 = blockIdx.y * 64, n0 = blockIdx.x * 64;
    int tid = threadIdx.x;
    int ty = tid >> 4, tx = tid & 15;
    int lr = tid >> 2, lseg = tid & 3;
    if (tid < 64) colsum[tid] = 0.f;
    float acc[4][4];
    #pragma unroll
    for (int i = 0; i < 4; i++)
        #pragma unroll
        for (int j = 0; j < 4; j++) acc[i][j] = 0.f;
    for (int d0 = 0; d0 < 256; d0 += 16) {
        __syncthreads();
        float4 va = *(const float4*)(g_H1 + (size_t)(m0 + lr) * 256 + d0 + lseg * 4);
        As[lseg * 4 + 0][lr] = va.x; As[lseg * 4 + 1][lr] = va.y;
        As[lseg * 4 + 2][lr] = va.z; As[lseg * 4 + 3][lr] = va.w;
        float4 vb = *(const float4*)(Bm + (size_t)(n0 + lr) * 256 + d0 + lseg * 4);
        Bs[lseg * 4 + 0][lr] = vb.x; Bs[lseg * 4 + 1][lr] = vb.y;
        Bs[lseg * 4 + 2][lr] = vb.z; Bs[lseg * 4 + 3][lr] = vb.w;
        __syncthreads();
        #pragma unroll
        for (int kk = 0; kk < 16; kk++) {
            float4 a = *(float4*)&As[kk][ty * 4];
            float4 b = *(float4*)&Bs[kk][tx * 4];
            float ar[4] = {a.x, a.y, a.z, a.w};
            float br[4] = {b.x, b.y, b.z, b.w};
            #pragma unroll
            for (int i = 0; i < 4; i++)
                #pragma unroll
                for (int j = 0; j < 4; j++) acc[i][j] += ar[i] * br[j];
        }
    }
    float sqtot = 0.f;
    float csumj[4] = {0.f, 0.f, 0.f, 0.f};
    #pragma unroll
    for (int i = 0; i < 4; i++) {
        size_t row = (size_t)(m0 + ty * 4 + i);
        float4 v = make_float4(acc[i][0], acc[i][1], acc[i][2], acc[i][3]);
        *(float4*)(g_CB + row * 256 + n0 + tx * 4) = v;
        float rsq = v.x * v.x + v.y * v.y + v.z * v.z + v.w * v.w;
        sqtot += rsq;
        float rm = fmaxf(fmaxf(fabsf(v.x), fabsf(v.y)), fmaxf(fabsf(v.z), fabsf(v.w)));
        #pragma unroll
        for (int o = 8; o; o >>= 1) {
            rsq += __shfl_xor_sync(0xffffffffu, rsq, o, 16);
            rm = fmaxf(rm, __shfl_xor_sync(0xffffffffu, rm, o, 16));
        }
        if (tx == 0) {
            atomicAdd(&g_cbsq[row], rsq);
            atomicMax(&g_cmaxb[row], __float_as_uint(rm));
        }
        csumj[0] += v.x; csumj[1] += v.y; csumj[2] += v.z; csumj[3] += v.w;
    }
    #pragma unroll
    for (int j = 0; j < 4; j++) atomicAdd(&colsum[tx * 4 + j], csumj[j]);
    float bs = blockReduceSum(sqtot);
    if (tid == 0) atomicAdd(&g_scal[1], bs);
    __syncthreads();
    if (tid < 64) atomicAdd(&g_csum[n0 + tid], colsum[tid]);
}

// -------- quantize z to int8 (token-major), global scale --------
__global__ void __launch_bounds__(256) zquant() {
    int t = blockIdx.x * 256 + threadIdx.x;          // < 524288
    float si = 127.f / __uint_as_float(g_maxzb);
    uint4 vh = *(const uint4*)(g_Zhi + (size_t)t * 8);
    uint4 vl = *(const uint4*)(g_Zlo + (size_t)t * 8);
    const __nv_bfloat162* hp = (const __nv_bfloat162*)&vh;
    const __nv_bfloat162* lp = (const __nv_bfloat162*)&vl;
    uint32_t p0 = 0, p1 = 0;
    #pragma unroll
    for (int j = 0; j < 4; j++) {
        float2 fh = __bfloat1622float2(hp[j]);
        float2 fl = __bfloat1622float2(lp[j]);
        int q0 = __float2int_rn((fh.x + fl.x) * si);
        int q1 = __float2int_rn((fh.y + fl.y) * si);
        if (j < 2) {
            p0 |= (uint32_t)(q0 & 0xff) << (16 * j);
            p0 |= (uint32_t)(q1 & 0xff) << (16 * j + 8);
        } else {
            p1 |= (uint32_t)(q0 & 0xff) << (16 * (j - 2));
            p1 |= (uint32_t)(q1 & 0xff) << (16 * (j - 2) + 8);
        }
    }
    *(uint2*)(g_Zq + (size_t)t * 8) = make_uint2(p0, p1);
}

// -------- quantize CB to int8 (per-row scale) + combined factor --------
__global__ void __launch_bounds__(256) cbquant() {
    int t = blockIdx.x * 256 + threadIdx.x;          // < 262144
    int row = t >> 5, seg = t & 31;
    float cm = __uint_as_float(g_cmaxb[row]);
    float si = cm > 0.f ? 127.f / cm : 0.f;
    const float4* p = (const float4*)(g_CB + (size_t)row * 256 + seg * 8);
    float4 a = p[0], b = p[1];
    float f[8] = {a.x, a.y, a.z, a.w, b.x, b.y, b.z, b.w};
    uint32_t p0 = 0, p1 = 0;
    #pragma unroll
    for (int j = 0; j < 4; j++) {
        int q = __float2int_rn(f[j] * si);
        p0 |= (uint32_t)(q & 0xff) << (8 * j);
    }
    #pragma unroll
    for (int j = 0; j < 4; j++) {
        int q = __float2int_rn(f[4 + j] * si);
        p1 |= (uint32_t)(q & 0xff) << (8 * j);
    }
    *(uint2*)(g_CBq + (size_t)row * 256 + seg * 8) = make_uint2(p0, p1);
    if (seg == 0) {
        float zm = __uint_as_float(g_maxzb);
        g_cf[row] = -2.f * (zm / 127.f) * (cm / 127.f);
    }
}

// ======== int8 HMMA approx distance: 128x128 CTA, 8 warps 32x64 ========
// BK=64 int8 (64B rows, swizzle c^((r>>1)&3)), 16KB stages, 3-stage ring.
#define STAGE_BYTES 16384
#define SM_CBSQ     (3 * STAGE_BYTES)
#define SM_CF       (SM_CBSQ + 512)
#define SM_BEST     (SM_CF + 512)
#define SM_THRESH   (SM_BEST + 1024)
#define DIST_SMEM   (SM_THRESH + 512)

__device__ __forceinline__ void issue_chunk(uint32_t sb_stage, int m0, int n0,
                                            int kc, int tid) {
    int k0 = kc * 64;
    int r = tid >> 1, cb = (tid & 1) * 2;
    #pragma unroll
    for (int i = 0; i < 2; i++) {
        int c = cb + i;
        uint32_t so = (uint32_t)(r * 64 + ((c ^ ((r >> 1) & 3)) << 4));
        cpa16(sb_stage + so,        g_Zq + (size_t)(m0 + r) * 256 + k0 + c * 16);
        cpa16(sb_stage + 8192 + so, g_CBq + (size_t)(n0 + r) * 256 + k0 + c * 16);
    }
    CP_COMMIT();
}

__global__ void __launch_bounds__(256, 2) dist_approx() {
    extern __shared__ __align__(1024) char smem[];
    uint32_t sb = smem_to_u32(smem);
    float* cbsq_s = (float*)(smem + SM_CBSQ);
    float* cf_s = (float*)(smem + SM_CF);
    unsigned long long* bestsh = (unsigned long long*)(smem + SM_BEST);
    float* threshsh = (float*)(smem + SM_THRESH);

    int tid = threadIdx.x, lane = tid & 31, wid = tid >> 5;
    int warp_m = wid >> 1, warp_n = wid & 1;
    int m0 = blockIdx.y * 128, n0 = blockIdx.x * 128;

    if (tid < 128) {
        cbsq_s[tid] = g_cbsq[n0 + tid];
        cf_s[tid] = g_cf[n0 + tid];
        bestsh[tid] = ~0ull;
    }

    int la7 = lane & 7, l3 = (lane >> 3) & 1, l4 = lane >> 4, l34 = lane >> 3;
    uint32_t aoff[2]; int aswz[2];
    #pragma unroll
    for (int mi = 0; mi < 2; mi++) {
        int r = warp_m * 32 + mi * 16 + la7 + l3 * 8;
        aoff[mi] = (uint32_t)(r * 64);
        aswz[mi] = (r >> 1) & 3;
    }
    uint32_t baddr[8];
    #pragma unroll
    for (int g = 0; g < 8; g++) {
        int r = warp_n * 64 + g * 8 + la7;
        baddr[g] = (uint32_t)(8192 + r * 64 + ((l34 ^ ((r >> 1) & 3)) << 4));
    }

    int acc[2][8][4];
    #pragma unroll
    for (int mi = 0; mi < 2; mi++)
        #pragma unroll
        for (int g = 0; g < 8; g++)
            #pragma unroll
            for (int q = 0; q < 4; q++) acc[mi][g][q] = 0;

    issue_chunk(sb, m0, n0, 0, tid);
    issue_chunk(sb + STAGE_BYTES, m0, n0, 1, tid);

    for (int kc = 0; kc < 4; kc++) {
        CP_WAIT1();
        __syncthreads();
        if (kc + 2 < 4)
            issue_chunk(sb + ((kc + 2) % 3) * STAGE_BYTES, m0, n0, kc + 2, tid);
        uint32_t st = sb + (kc % 3) * STAGE_BYTES;
        uint32_t Af[2][2][4];
        #pragma unroll
        for (int mi = 0; mi < 2; mi++)
            #pragma unroll
            for (int ki = 0; ki < 2; ki++) {
                uint32_t csel = (uint32_t)(((2 * ki + l4) ^ aswz[mi]) << 4);
                ldsm4(Af[mi][ki], st + aoff[mi] + csel);
            }
        #pragma unroll
        for (int gp = 0; gp < 4; gp++) {
            uint32_t B0[4], B1[4];
            ldsm4(B0, st + baddr[2 * gp]);
            ldsm4(B1, st + baddr[2 * gp + 1]);
            mma_s8(acc[0][2 * gp],     Af[0][0], B0[0], B0[1]);
            mma_s8(acc[1][2 * gp],     Af[1][0], B0[0], B0[1]);
            mma_s8(acc[0][2 * gp + 1], Af[0][0], B1[0], B1[1]);
            mma_s8(acc[1][2 * gp + 1], Af[1][0], B1[0], B1[1]);
            mma_s8(acc[0][2 * gp],     Af[0][1], B0[2], B0[3]);
            mma_s8(acc[1][2 * gp],     Af[1][1], B0[2], B0[3]);
            mma_s8(acc[0][2 * gp + 1], Af[0][1], B1[2], B1[3]);
            mma_s8(acc[1][2 * gp + 1], Af[1][1], B1[2], B1[3]);
        }
    }

    // ---- pass 1: local argmin, quad reduce, atomicMin ----
    float bestvt[4];
    #pragma unroll
    for (int mi = 0; mi < 2; mi++)
        #pragma unroll
        for (int h = 0; h < 2; h++) {
            int rloc = warp_m * 32 + mi * 16 + (lane >> 2) + h * 8;
            float bestv = 3.4e38f;
            int besti = 0;
            #pragma unroll
            for (int g = 0; g < 8; g++)
                #pragma unroll
                for (int e = 0; e < 2; e++) {
                    int col = warp_n * 64 + g * 8 + (lane & 3) * 2 + e;
                    float sc = fmaf(cf_s[col], (float)acc[mi][g][h * 2 + e],
                                    cbsq_s[col]);
                    if (sc < bestv) { bestv = sc; besti = n0 + col; }
                }
            bestvt[mi * 2 + h] = bestv;
            uint32_t fb = __float_as_uint(bestv);
            uint32_t key = (fb & 0x80000000u) ? ~fb : (fb | 0x80000000u);
            unsigned long long best =
                ((unsigned long long)key << 32) | (unsigned)besti;
            unsigned long long o1 = __shfl_xor_sync(0xffffffffu, best, 1);
            best = best < o1 ? best : o1;
            unsigned long long o2 = __shfl_xor_sync(0xffffffffu, best, 2);
            best = best < o2 ? best : o2;
            if ((lane & 3) == 0) atomicMin(&bestsh[rloc], best);
        }
    __syncthreads();
    if (tid < 128) {
        unsigned long long mine = bestsh[tid];
        unsigned long long old = atomicMin(&g_best[m0 + tid], mine);
        unsigned long long merged = old < mine ? old : mine;
        uint32_t key = (uint32_t)(merged >> 32);
        uint32_t fb = (key & 0x80000000u) ? (key & 0x7fffffffu) : ~key;
        threshsh[tid] = __uint_as_float(fb) + MARGIN;
    }
    __syncthreads();

    // ---- pass 2: push candidates (skip-guarded) ----
    #pragma unroll
    for (int mi = 0; mi < 2; mi++)
        #pragma unroll
        for (int h = 0; h < 2; h++) {
            int rloc = warp_m * 32 + mi * 16 + (lane >> 2) + h * 8;
            float th = threshsh[rloc];
            if (bestvt[mi * 2 + h] > th) continue;
            int token = m0 + rloc;
            #pragma unroll
            for (int g = 0; g < 8; g++)
                #pragma unroll
                for (int e = 0; e < 2; e++) {
                    int col = warp_n * 64 + g * 8 + (lane & 3) * 2 + e;
                    float sc = fmaf(cf_s[col], (float)acc[mi][g][h * 2 + e],
                                    cbsq_s[col]);
                    if (sc <= th) {
                        int ix = atomicAdd(&g_ccount[token], 1);
                        if (ix < CAP)
                            g_cand[(size_t)token * CAP + ix] =
                                (unsigned short)(n0 + col);
                    }
                }
        }
}

// ======== refine: exact fp32 re-score (full-scan fallback on overflow) ======
__global__ void __launch_bounds__(256) refine() {
    int wid = threadIdx.x >> 5, lane = threadIdx.x & 31;
    int n = blockIdx.x * 8 + wid;
    int cntraw = g_ccount[n];

    uint4 vh = *(const uint4*)(g_Zhi + (size_t)n * 256 + lane * 8);
    uint4 vl = *(const uint4*)(g_Zlo + (size_t)n * 256 + lane * 8);
    float zf[8];
    {
        const __nv_bfloat162* hp = (const __nv_bfloat162*)&vh;
        const __nv_bfloat162* lp = (const __nv_bfloat162*)&vl;
        #pragma unroll
        for (int t = 0; t < 4; t++) {
            float2 fh = __bfloat1622float2(hp[t]);
            float2 fl = __bfloat1622float2(lp[t]);
            zf[2 * t] = fh.x + fl.x;
            zf[2 * t + 1] = fh.y + fl.y;
        }
    }

    unsigned long long best = ~0ull;
    if (cntraw <= CAP) {
        const unsigned short* cl = g_cand + (size_t)n * CAP;
        for (int c = 0; c < cntraw; c++) {
            int code = cl[c];
            const float4* cb = (const float4*)(g_CB + (size_t)code * 256 + lane * 8);
            float4 c0 = cb[0], c1 = cb[1];
            float d = zf[0] * c0.x + zf[1] * c0.y + zf[2] * c0.z + zf[3] * c0.w
                    + zf[4] * c1.x + zf[5] * c1.y + zf[6] * c1.z + zf[7] * c1.w;
            #pragma unroll
            for (int o = 16; o; o >>= 1) d += __shfl_xor_sync(0xffffffffu, d, o);
            float sc = fmaf(-2.f, d, g_cbsq[code]);
            uint32_t fb = __float_as_uint(sc);
            uint32_t key = (fb & 0x80000000u) ? ~fb : (fb | 0x80000000u);
            unsigned long long u = ((unsigned long long)key << 32) | (unsigned)code;
            best = best < u ? best : u;
        }
    } else {
        for (int code = 0; code < KK; code++) {
            const float4* cb = (const float4*)(g_CB + (size_t)code * 256 + lane * 8);
            float4 c0 = cb[0], c1 = cb[1];
            float d = zf[0] * c0.x + zf[1] * c0.y + zf[2] * c0.z + zf[3] * c0.w
                    + zf[4] * c1.x + zf[5] * c1.y + zf[6] * c1.z + zf[7] * c1.w;
            #pragma unroll
            for (int o = 16; o; o >>= 1) d += __shfl_xor_sync(0xffffffffu, d, o);
            float sc = fmaf(-2.f, d, g_cbsq[code]);
            uint32_t fb = __float_as_uint(sc);
            uint32_t key = (fb & 0x80000000u) ? ~fb : (fb | 0x80000000u);
            unsigned long long u = ((unsigned long long)key << 32) | (unsigned)code;
            best = best < u ? best : u;
        }
    }
    if (lane == 0) g_best[n] = best;
}

// -------- gather z_q + loss + histogram --------
__global__ void __launch_bounds__(256) gather_loss(const float* __restrict__ z,
                                                   float* __restrict__ out) {
    int x = blockIdx.x;                 // 0..511
    int b = x >> 8, s0 = (x & 255) * 32;
    int t = threadIdx.x;
    int s = s0 + (t & 31);
    int d4b = t >> 5;                   // 0..7
    int n = b * THW + s;
    int id = (int)(unsigned int)(g_best[n] & 0xffffffffull);
    if (t < 32) atomicAdd(&g_counts[id], 1);
    const float* cbrow = g_CB + (size_t)id * 256;
    size_t ebase = ((size_t)b << 21) + s;
    float lsum = 0.f;
    #pragma unroll 4
    for (int it = 0; it < 8; it++) {
        int d4 = d4b + 8 * it;
        float4 q = *(const float4*)(cbrow + d4 * 4);
        size_t e = ebase + (size_t)(d4 * 4) * THW;
        float z0 = z[e];            out[e] = q.x;
        float z1 = z[e + THW];      out[e + THW] = q.y;
        float z2 = z[e + 2 * THW];  out[e + 2 * THW] = q.z;
        float z3 = z[e + 3 * THW];  out[e + 3 * THW] = q.w;
        float d0 = q.x - z0, d1 = q.y - z1, d2 = q.z - z2, d3 = q.w - z3;
        lsum += d0 * d0 + d1 * d1 + d2 * d2 + d3 * d3;
    }
    float ls = blockReduceSum(lsum);
    if (t == 0) atomicAdd(&g_scal[2], ls);
}

// -------- finalize scalars --------
__global__ void __launch_bounds__(256) finalize(float* __restrict__ out) {
    float ps = 0.f;
    for (int k = threadIdx.x; k < KK; k += 256) {
        float e = (float)g_counts[k] * (1.f / (float)NN);
        ps += e * logf(e + 1e-10f);
    }
    float ent = blockReduceSum(ps);
    float dp = (g_zcol[threadIdx.x] * (1.f / (float)NN)) *
               (g_csum[threadIdx.x] * (1.f / (float)KK));
    float dot = blockReduceSum(dp);
    if (threadIdx.x == 0) {
        float loss = 1.25f * g_scal[2] / (float)((size_t)NN * DD);
        float perp = expf(-ent);
        float meand = g_scal[0] / (float)NN + g_scal[1] / (float)KK - 2.f * dot;
        out[4194304] = loss;
        out[4194305] = perp;
        out[4194306] = meand;
    }
}

extern "C" void kernel_launch(void* const* d_in, const int* in_sizes, int n_in,
                              void* d_out, int out_size) {
    const float* z   = (const float*)d_in[0];
    const float* emb = (const float*)d_in[1];
    const float* w1  = (const float*)d_in[2];
    const float* w2  = (const float*)d_in[3];
    float* out = (float*)d_out;

    static int attr_done = 0;
    if (!attr_done) {
        cudaFuncSetAttribute(dist_approx, cudaFuncAttributeMaxDynamicSharedMemorySize,
                             DIST_SMEM);
        attr_done = 1;
    }

    k_init<<<64, 256>>>();
    fused_pre<<<dim3(4, 128, 2), 256>>>(z, emb, w1);
    zquant<<<2048, 256>>>();
    gemm_cb<<<dim3(4, 128), 256>>>(w2);
    cbquant<<<1024, 256>>>();
    dist_approx<<<dim3(64, 128), 256, DIST_SMEM>>>();
    refine<<<2048, 256>>>();
    gather_loss<<<512, 256>>>(z, out);
    finalize<<<1, 256>>>(out);
}

// round 15
// speedup vs baseline: 1.7430x; 1.7430x over previous
#include <cuda_runtime.h>
#include <cuda_bf16.h>
#include <math.h>
#include <stdint.h>

// Problem constants (fixed by the dataset)
#define BB   2
#define DD   256
#define THW  8192
#define NN   16384
#define KK   8192

#define MARGIN 0.125f
#define CAP    1024

// -------- device scratch (no allocations allowed) --------
__device__ float g_H1[KK * DD];
__device__ float g_CB[KK * DD];
__device__ __nv_bfloat16 g_CBhi[KK * DD];
__device__ __nv_bfloat16 g_Zhi[NN * DD];
__device__ __nv_bfloat16 g_Zlo[NN * DD];
__device__ float g_cbsq[KK];
__device__ float g_csum[DD];
__device__ float g_zcol[DD];
__device__ float g_scal[3];
__device__ unsigned long long g_best[NN];
__device__ int   g_counts[KK];
__device__ int   g_ccount[NN];
__device__ unsigned short g_cand[(size_t)NN * CAP];   // 32 MB

// ================= PTX helpers (base sm_103-safe) =====
__device__ __forceinline__ uint32_t smem_to_u32(const void* p) {
    uint32_t a;
    asm("{ .reg .u64 t; cvta.to.shared.u64 t, %1; cvt.u32.u64 %0, t; }" : "=r"(a) : "l"(p));
    return a;
}
__device__ __forceinline__ void cpa16(uint32_t saddr, const void* g) {
    asm volatile("cp.async.cg.shared.global [%0], [%1], 16;" :: "r"(saddr), "l"(g) : "memory");
}
#define CP_COMMIT() asm volatile("cp.async.commit_group;" ::: "memory")
#define CP_WAIT1()  asm volatile("cp.async.wait_group 1;" ::: "memory")

__device__ __forceinline__ void ldsm4(uint32_t (&r)[4], uint32_t addr) {
    asm volatile("ldmatrix.sync.aligned.m8n8.x4.shared.b16 {%0,%1,%2,%3}, [%4];"
        : "=r"(r[0]), "=r"(r[1]), "=r"(r[2]), "=r"(r[3]) : "r"(addr));
}
__device__ __forceinline__ void mma16816(float (&d)[4], const uint32_t (&a)[4],
                                         uint32_t b0, uint32_t b1) {
    asm volatile("mma.sync.aligned.m16n8k16.row.col.f32.bf16.bf16.f32 "
        "{%0,%1,%2,%3}, {%4,%5,%6,%7}, {%8,%9}, {%0,%1,%2,%3};"
        : "+f"(d[0]), "+f"(d[1]), "+f"(d[2]), "+f"(d[3])
        : "r"(a[0]), "r"(a[1]), "r"(a[2]), "r"(a[3]), "r"(b0), "r"(b1));
}

// -------- helpers --------
__device__ __forceinline__ float blockReduceSum(float v) {
    __shared__ float sh[32];
    int lane = threadIdx.x & 31, w = threadIdx.x >> 5;
    #pragma unroll
    for (int o = 16; o; o >>= 1) v += __shfl_xor_sync(0xffffffffu, v, o);
    if (lane == 0) sh[w] = v;
    __syncthreads();
    v = (threadIdx.x < (blockDim.x >> 5)) ? sh[threadIdx.x] : 0.f;
    if (w == 0) {
        #pragma unroll
        for (int o = 16; o; o >>= 1) v += __shfl_xor_sync(0xffffffffu, v, o);
    }
    __syncthreads();
    return v;
}

__global__ void k_init() {
    int t = blockIdx.x * blockDim.x + threadIdx.x;
    if (t < NN) { g_best[t] = ~0ull; g_ccount[t] = 0; }
    if (t < KK) { g_counts[t] = 0; g_cbsq[t] = 0.f; }
    if (t < DD) { g_csum[t] = 0.f; g_zcol[t] = 0.f; }
    if (t < 3)  g_scal[t] = 0.f;
}

// ===== double-buffered fp32 GEMM core: acc += A[64,256] @ B[64,256]^T tile ==
// As/Bs are [2][32][64] (transposed k-major). One __syncthreads per k-chunk.
__device__ __forceinline__ void gemm_body(const float* __restrict__ A,
                                          const float* __restrict__ Bm,
                                          int m0, int n0, int tid,
                                          float (*As)[64], float (*Bs)[64],
                                          float (&acc)[4][4]) {
    int ty = tid >> 4, tx = tid & 15;
    int lr = tid >> 2, lseg = tid & 3;
    const float* Ap = A + (size_t)(m0 + lr) * 256 + lseg * 4;
    const float* Bp = Bm + (size_t)(n0 + lr) * 256 + lseg * 4;

    float4 ra0, ra1, rb0, rb1;
    // prologue: tile 0 -> regs -> buf0
    ra0 = *(const float4*)(Ap);      ra1 = *(const float4*)(Ap + 16);
    rb0 = *(const float4*)(Bp);      rb1 = *(const float4*)(Bp + 16);
    #pragma unroll
    for (int j = 0; j < 4; j++) {
        As[lseg * 4 + j][lr]      = ((const float*)&ra0)[j];
        As[16 + lseg * 4 + j][lr] = ((const float*)&ra1)[j];
        Bs[lseg * 4 + j][lr]      = ((const float*)&rb0)[j];
        Bs[16 + lseg * 4 + j][lr] = ((const float*)&rb1)[j];
    }
    // preload tile 1 into regs
    ra0 = *(const float4*)(Ap + 32); ra1 = *(const float4*)(Ap + 48);
    rb0 = *(const float4*)(Bp + 32); rb1 = *(const float4*)(Bp + 48);
    __syncthreads();

    #pragma unroll
    for (int s = 0; s < 8; s++) {
        float (*Asc)[64] = As + (s & 1) * 32;
        float (*Bsc)[64] = Bs + (s & 1) * 32;
        // store preloaded regs to other buffer
        if (s + 1 < 8) {
            float (*Asn)[64] = As + ((s + 1) & 1) * 32;
            float (*Bsn)[64] = Bs + ((s + 1) & 1) * 32;
            #pragma unroll
            for (int j = 0; j < 4; j++) {
                Asn[lseg * 4 + j][lr]      = ((const float*)&ra0)[j];
                Asn[16 + lseg * 4 + j][lr] = ((const float*)&ra1)[j];
                Bsn[lseg * 4 + j][lr]      = ((const float*)&rb0)[j];
                Bsn[16 + lseg * 4 + j][lr] = ((const float*)&rb1)[j];
            }
        }
        // preload tile s+2
        if (s + 2 < 8) {
            int d0 = (s + 2) * 32;
            ra0 = *(const float4*)(Ap + d0);      ra1 = *(const float4*)(Ap + d0 + 16);
            rb0 = *(const float4*)(Bp + d0);      rb1 = *(const float4*)(Bp + d0 + 16);
        }
        #pragma unroll
        for (int kk = 0; kk < 32; kk++) {
            float4 a = *(float4*)&Asc[kk][ty * 4];
            float4 b = *(float4*)&Bsc[kk][tx * 4];
            float ar[4] = {a.x, a.y, a.z, a.w};
            float br[4] = {b.x, b.y, b.z, b.w};
            #pragma unroll
            for (int i = 0; i < 4; i++)
                #pragma unroll
                for (int j = 0; j < 4; j++) acc[i][j] += ar[i] * br[j];
        }
        __syncthreads();
    }
}

// ======== fused: gemm0 (H1 = gelu(emb @ w1^T)) [z==0] + zsplit [z==1] ========
__global__ void __launch_bounds__(256) fused_pre(const float* __restrict__ z,
                                                 const float* __restrict__ emb,
                                                 const float* __restrict__ w1) {
    __shared__ __align__(16) float sh[8384];
    int tid = threadIdx.x;

    if (blockIdx.z == 0) {
        float (*As)[64] = (float (*)[64])sh;              // [2][32][64] = 4096
        float (*Bs)[64] = (float (*)[64])(sh + 4096);     // [2][32][64] = 4096
        int m0 = blockIdx.y * 64, n0 = blockIdx.x * 64;
        int ty = tid >> 4, tx = tid & 15;
        float acc[4][4];
        #pragma unroll
        for (int i = 0; i < 4; i++)
            #pragma unroll
            for (int j = 0; j < 4; j++) acc[i][j] = 0.f;
        gemm_body(emb, w1, m0, n0, tid, As, Bs, acc);
        #pragma unroll
        for (int i = 0; i < 4; i++)
            #pragma unroll
            for (int j = 0; j < 4; j++) {
                float x = acc[i][j];
                g_H1[(size_t)(m0 + ty * 4 + i) * 256 + n0 + tx * 4 + j] =
                    0.5f * x * (1.f + erff(x * 0.70710678118654752f));
            }
        return;
    }

    // ---------------- zsplit: transpose + bf16 split + stats ----------------
    float (*sm)[261] = (float (*)[261])sh;
    float* zc = sh + 8352;
    int idx = blockIdx.y * 4 + blockIdx.x;
    int s0 = (idx & 31) * 256, d0 = ((idx >> 5) & 7) * 32, b = idx >> 8;
    if (tid < 32) zc[tid] = 0.f;
    const float* zp = z + ((size_t)b * 256 + d0) * THW + s0;
    #pragma unroll
    for (int i = 0; i < 32; i++) sm[i][tid] = zp[(size_t)i * THW + tid];
    __syncthreads();
    {
        int i = tid & 31, c = tid >> 5;
        float s = 0.f, s2 = 0.f;
        #pragma unroll
        for (int u = 0; u < 32; u++) {
            float v = sm[i][c * 32 + u];
            s += v; s2 += v * v;
        }
        atomicAdd(&zc[i], s);
        float ts2 = blockReduceSum(s2);
        if (tid == 0) atomicAdd(&g_scal[0], ts2);
    }
    int dseg = tid & 7, sl = tid >> 3;
    #pragma unroll
    for (int w = 0; w < 8; w++) {
        int s_i = w * 32 + sl;
        float x0 = sm[dseg * 4 + 0][s_i];
        float x1 = sm[dseg * 4 + 1][s_i];
        float x2 = sm[dseg * 4 + 2][s_i];
        float x3 = sm[dseg * 4 + 3][s_i];
        __nv_bfloat16 h0 = __float2bfloat16_rn(x0), h1 = __float2bfloat16_rn(x1);
        __nv_bfloat16 h2 = __float2bfloat16_rn(x2), h3 = __float2bfloat16_rn(x3);
        __nv_bfloat162 hp0 = __halves2bfloat162(h0, h1);
        __nv_bfloat162 hp1 = __halves2bfloat162(h2, h3);
        __nv_bfloat16 l0 = __float2bfloat16_rn(x0 - __bfloat162float(h0));
        __nv_bfloat16 l1 = __float2bfloat16_rn(x1 - __bfloat162float(h1));
        __nv_bfloat16 l2 = __float2bfloat16_rn(x2 - __bfloat162float(h2));
        __nv_bfloat16 l3 = __float2bfloat16_rn(x3 - __bfloat162float(h3));
        __nv_bfloat162 lp0 = __halves2bfloat162(l0, l1);
        __nv_bfloat162 lp1 = __halves2bfloat162(l2, l3);
        size_t base = ((size_t)(b * THW + s0 + s_i) * 256) + d0 + dseg * 4;
        *(uint2*)(g_Zhi + base) = make_uint2(*reinterpret_cast<uint32_t*>(&hp0),
                                             *reinterpret_cast<uint32_t*>(&hp1));
        *(uint2*)(g_Zlo + base) = make_uint2(*reinterpret_cast<uint32_t*>(&lp0),
                                             *reinterpret_cast<uint32_t*>(&lp1));
    }
    __syncthreads();
    if (tid < 32) atomicAdd(&g_zcol[d0 + tid], zc[tid]);
}

// -------- gemm1: CB = H1 @ w2^T, fused split/stats epilogue --------
__global__ void __launch_bounds__(256) gemm_cb(const float* __restrict__ Bm) {
    __shared__ __align__(16) float sh[8192];
    __shared__ float colsum[64];
    float (*As)[64] = (float (*)[64])sh;
    float (*Bs)[64] = (float (*)[64])(sh + 4096);
    int m0 = blockIdx.y * 64, n0 = blockIdx.x * 64;
    int tid = threadIdx.x;
    int ty = tid >> 4, tx = tid & 15;
    if (tid < 64) colsum[tid] = 0.f;
    float acc[4][4];
    #pragma unroll
    for (int i = 0; i < 4; i++)
        #pragma unroll
        for (int j = 0; j < 4; j++) acc[i][j] = 0.f;
    gemm_body(g_H1, Bm, m0, n0, tid, As, Bs, acc);

    float sqtot = 0.f;
    float csumj[4] = {0.f, 0.f, 0.f, 0.f};
    #pragma unroll
    for (int i = 0; i < 4; i++) {
        size_t row = (size_t)(m0 + ty * 4 + i);
        float4 v = make_float4(acc[i][0], acc[i][1], acc[i][2], acc[i][3]);
        *(float4*)(g_CB + row * 256 + n0 + tx * 4) = v;
        uint32_t hw[2];
        float xs[4] = {v.x, v.y, v.z, v.w};
        #pragma unroll
        for (int t = 0; t < 2; t++) {
            __nv_bfloat16 h0 = __float2bfloat16_rn(xs[2 * t]);
            __nv_bfloat16 h1 = __float2bfloat16_rn(xs[2 * t + 1]);
            __nv_bfloat162 hp = __halves2bfloat162(h0, h1);
            hw[t] = *reinterpret_cast<uint32_t*>(&hp);
        }
        *(uint2*)(g_CBhi + row * 256 + n0 + tx * 4) = make_uint2(hw[0], hw[1]);
        float rsq = v.x * v.x + v.y * v.y + v.z * v.z + v.w * v.w;
        sqtot += rsq;
        #pragma unroll
        for (int o = 8; o; o >>= 1) rsq += __shfl_xor_sync(0xffffffffu, rsq, o, 16);
        if (tx == 0) atomicAdd(&g_cbsq[m0 + ty * 4 + i], rsq);
        csumj[0] += v.x; csumj[1] += v.y; csumj[2] += v.z; csumj[3] += v.w;
    }
    #pragma unroll
    for (int j = 0; j < 4; j++) atomicAdd(&colsum[tx * 4 + j], csumj[j]);
    float bs = blockReduceSum(sqtot);
    if (tid == 0) atomicAdd(&g_scal[1], bs);
    __syncthreads();
    if (tid < 64) atomicAdd(&g_csum[n0 + tid], colsum[tid]);
}

// ======== approx HMMA distance (hi*hi only) + candidate push (R7 proven) ====
#define STAGE_BYTES 16384
#define SM_CBSQ     (3 * STAGE_BYTES)
#define SM_BEST     (SM_CBSQ + 512)
#define SM_THRESH   (SM_BEST + 1024)
#define DIST_SMEM   (SM_THRESH + 512)

__device__ __forceinline__ void issue_chunk(uint32_t sb_stage, int m0, int n0,
                                            int kc, int tid) {
    int row = tid >> 2, c = tid & 3;
    int k0 = kc * 32;
    #pragma unroll
    for (int half = 0; half < 2; half++) {
        int r = row + half * 64;
        uint32_t so = (uint32_t)(r * 64 + ((c ^ ((r >> 1) & 3)) << 4));
        cpa16(sb_stage + so,        g_Zhi + (size_t)(m0 + r) * 256 + k0 + c * 8);
        cpa16(sb_stage + 8192 + so, g_CBhi + (size_t)(n0 + r) * 256 + k0 + c * 8);
    }
    CP_COMMIT();
}

__global__ void __launch_bounds__(256, 2) dist_approx() {
    extern __shared__ __align__(1024) char smem[];
    uint32_t sb = smem_to_u32(smem);
    float* cbsq_s = (float*)(smem + SM_CBSQ);
    unsigned long long* bestsh = (unsigned long long*)(smem + SM_BEST);
    float* threshsh = (float*)(smem + SM_THRESH);

    int tid = threadIdx.x, lane = tid & 31, wid = tid >> 5;
    int warp_m = wid >> 1, warp_n = wid & 1;
    int m0 = blockIdx.y * 128, n0 = blockIdx.x * 128;

    if (tid < 128) { cbsq_s[tid] = g_cbsq[n0 + tid]; bestsh[tid] = ~0ull; }

    int la7 = lane & 7, l3 = (lane >> 3) & 1, l4 = lane >> 4;
    uint32_t aoff[2]; int aswz[2];
    #pragma unroll
    for (int mi = 0; mi < 2; mi++) {
        int r = warp_m * 32 + mi * 16 + la7 + l3 * 8;
        aoff[mi] = (uint32_t)(r * 64);
        aswz[mi] = (r >> 1) & 3;
    }
    uint32_t boff[4]; int bswz[4];
    #pragma unroll
    for (int g = 0; g < 4; g++) {
        int r = warp_n * 64 + g * 16 + la7 + l4 * 8;
        boff[g] = (uint32_t)(8192 + r * 64);
        bswz[g] = (r >> 1) & 3;
    }

    float acc[2][8][4];
    #pragma unroll
    for (int mi = 0; mi < 2; mi++)
        #pragma unroll
        for (int nj = 0; nj < 8; nj++)
            #pragma unroll
            for (int q = 0; q < 4; q++) acc[mi][nj][q] = 0.f;

    issue_chunk(sb, m0, n0, 0, tid);
    issue_chunk(sb + STAGE_BYTES, m0, n0, 1, tid);

    for (int kc = 0; kc < 8; kc++) {
        CP_WAIT1();
        __syncthreads();
        if (kc + 2 < 8)
            issue_chunk(sb + ((kc + 2) % 3) * STAGE_BYTES, m0, n0, kc + 2, tid);
        uint32_t st = sb + (kc % 3) * STAGE_BYTES;
        #pragma unroll
        for (int ki = 0; ki < 2; ki++) {
            uint32_t A0[2][4], Bb[4][4];
            #pragma unroll
            for (int mi = 0; mi < 2; mi++) {
                uint32_t csel = (uint32_t)(((2 * ki + l4) ^ aswz[mi]) << 4);
                ldsm4(A0[mi], st + aoff[mi] + csel);
            }
            #pragma unroll
            for (int g = 0; g < 4; g++) {
                uint32_t csel = (uint32_t)(((2 * ki + l3) ^ bswz[g]) << 4);
                ldsm4(Bb[g], st + boff[g] + csel);
            }
            #pragma unroll
            for (int mi = 0; mi < 2; mi++)
                #pragma unroll
                for (int g = 0; g < 4; g++) {
                    mma16816(acc[mi][2 * g],     A0[mi], Bb[g][0], Bb[g][1]);
                    mma16816(acc[mi][2 * g + 1], A0[mi], Bb[g][2], Bb[g][3]);
                }
        }
    }

    // ---- pass 1: local argmin, quad reduce, atomicMin ----
    float bestvt[4];
    #pragma unroll
    for (int mi = 0; mi < 2; mi++)
        #pragma unroll
        for (int h = 0; h < 2; h++) {
            int rloc = warp_m * 32 + mi * 16 + (lane >> 2) + h * 8;
            float bestv = 3.4e38f;
            int besti = 0;
            #pragma unroll
            for (int nj = 0; nj < 8; nj++)
                #pragma unroll
                for (int e = 0; e < 2; e++) {
                    int col = warp_n * 64 + nj * 8 + (lane & 3) * 2 + e;
                    float sc = fmaf(-2.f, acc[mi][nj][h * 2 + e], cbsq_s[col]);
                    if (sc < bestv) { bestv = sc; besti = n0 + col; }
                }
            bestvt[mi * 2 + h] = bestv;
            uint32_t fb = __float_as_uint(bestv);
            uint32_t key = (fb & 0x80000000u) ? ~fb : (fb | 0x80000000u);
            unsigned long long best =
                ((unsigned long long)key << 32) | (unsigned)besti;
            unsigned long long o1 = __shfl_xor_sync(0xffffffffu, best, 1);
            best = best < o1 ? best : o1;
            unsigned long long o2 = __shfl_xor_sync(0xffffffffu, best, 2);
            best = best < o2 ? best : o2;
            if ((lane & 3) == 0) atomicMin(&bestsh[rloc], best);
        }
    __syncthreads();
    if (tid < 128) {
        unsigned long long mine = bestsh[tid];
        unsigned long long old = atomicMin(&g_best[m0 + tid], mine);
        unsigned long long merged = old < mine ? old : mine;
        uint32_t key = (uint32_t)(merged >> 32);
        uint32_t fb = (key & 0x80000000u) ? (key & 0x7fffffffu) : ~key;
        threshsh[tid] = __uint_as_float(fb) + MARGIN;
    }
    __syncthreads();

    // ---- pass 2: push candidates (skip-guarded by pass-1 per-thread min) ----
    #pragma unroll
    for (int mi = 0; mi < 2; mi++)
        #pragma unroll
        for (int h = 0; h < 2; h++) {
            int rloc = warp_m * 32 + mi * 16 + (lane >> 2) + h * 8;
            float th = threshsh[rloc];
            if (bestvt[mi * 2 + h] > th) continue;
            int token = m0 + rloc;
            #pragma unroll
            for (int nj = 0; nj < 8; nj++)
                #pragma unroll
                for (int e = 0; e < 2; e++) {
                    int col = warp_n * 64 + nj * 8 + (lane & 3) * 2 + e;
                    float sc = fmaf(-2.f, acc[mi][nj][h * 2 + e], cbsq_s[col]);
                    if (sc <= th) {
                        int ix = atomicAdd(&g_ccount[token], 1);
                        if (ix < CAP)
                            g_cand[(size_t)token * CAP + ix] =
                                (unsigned short)(n0 + col);
                    }
                }
        }
}

// ======== refine: exact fp32 re-score of pushed candidates ========
__global__ void __launch_bounds__(256) refine() {
    int wid = threadIdx.x >> 5, lane = threadIdx.x & 31;
    int n = blockIdx.x * 8 + wid;
    int cnt = g_ccount[n];
    if (cnt > CAP) cnt = CAP;

    uint4 vh = *(const uint4*)(g_Zhi + (size_t)n * 256 + lane * 8);
    uint4 vl = *(const uint4*)(g_Zlo + (size_t)n * 256 + lane * 8);
    float zf[8];
    {
        const __nv_bfloat162* hp = (const __nv_bfloat162*)&vh;
        const __nv_bfloat162* lp = (const __nv_bfloat162*)&vl;
        #pragma unroll
        for (int t = 0; t < 4; t++) {
            float2 fh = __bfloat1622float2(hp[t]);
            float2 fl = __bfloat1622float2(lp[t]);
            zf[2 * t] = fh.x + fl.x;
            zf[2 * t + 1] = fh.y + fl.y;
        }
    }

    unsigned long long best = ~0ull;
    const unsigned short* cl = g_cand + (size_t)n * CAP;
    for (int c = 0; c < cnt; c++) {
        int code = cl[c];
        const float4* cb = (const float4*)(g_CB + (size_t)code * 256 + lane * 8);
        float4 c0 = cb[0], c1 = cb[1];
        float d = zf[0] * c0.x + zf[1] * c0.y + zf[2] * c0.z + zf[3] * c0.w
                + zf[4] * c1.x + zf[5] * c1.y + zf[6] * c1.z + zf[7] * c1.w;
        #pragma unroll
        for (int o = 16; o; o >>= 1) d += __shfl_xor_sync(0xffffffffu, d, o);
        float sc = fmaf(-2.f, d, g_cbsq[code]);
        uint32_t fb = __float_as_uint(sc);
        uint32_t key = (fb & 0x80000000u) ? ~fb : (fb | 0x80000000u);
        unsigned long long u = ((unsigned long long)key << 32) | (unsigned)code;
        best = best < u ? best : u;
    }
    if (lane == 0) g_best[n] = best;
}

// -------- gather z_q + loss + histogram (coalesced CB rows) --------
__global__ void __launch_bounds__(256) gather_loss(const float* __restrict__ z,
                                                   float* __restrict__ out) {
    int x = blockIdx.x;
    int b = x >> 7, s0 = (x & 127) * 64;
    int t = threadIdx.x;
    int s = s0 + (t & 63);
    int d4b = t >> 6;
    int n = b * THW + s;
    int id = (int)(unsigned int)(g_best[n] & 0xffffffffull);
    if (t < 64) atomicAdd(&g_counts[id], 1);
    const float* cbrow = g_CB + (size_t)id * 256;
    size_t ebase = ((size_t)b << 21) + s;
    float lsum = 0.f;
    #pragma unroll 4
    for (int it = 0; it < 16; it++) {
        int d4 = d4b + 4 * it;
        float4 q = *(const float4*)(cbrow + d4 * 4);
        size_t e = ebase + (size_t)(d4 * 4) * THW;
        float z0 = z[e];            out[e] = q.x;
        float z1 = z[e + THW];      out[e + THW] = q.y;
        float z2 = z[e + 2 * THW];  out[e + 2 * THW] = q.z;
        float z3 = z[e + 3 * THW];  out[e + 3 * THW] = q.w;
        float d0 = q.x - z0, d1 = q.y - z1, d2 = q.z - z2, d3 = q.w - z3;
        lsum += d0 * d0 + d1 * d1 + d2 * d2 + d3 * d3;
    }
    float ls = blockReduceSum(lsum);
    if (t == 0) atomicAdd(&g_scal[2], ls);
}

// -------- finalize scalars --------
__global__ void __launch_bounds__(256) finalize(float* __restrict__ out) {
    float ps = 0.f;
    for (int k = threadIdx.x; k < KK; k += 256) {
        float e = (float)g_counts[k] * (1.f / (float)NN);
        ps += e * logf(e + 1e-10f);
    }
    float ent = blockReduceSum(ps);
    float dp = (g_zcol[threadIdx.x] * (1.f / (float)NN)) *
               (g_csum[threadIdx.x] * (1.f / (float)KK));
    float dot = blockReduceSum(dp);
    if (threadIdx.x == 0) {
        float loss = 1.25f * g_scal[2] / (float)((size_t)NN * DD);
        float perp = expf(-ent);
        float meand = g_scal[0] / (float)NN + g_scal[1] / (float)KK - 2.f * dot;
        out[4194304] = loss;
        out[4194305] = perp;
        out[4194306] = meand;
    }
}

extern "C" void kernel_launch(void* const* d_in, const int* in_sizes, int n_in,
                              void* d_out, int out_size) {
    const float* z   = (const float*)d_in[0];
    const float* emb = (const float*)d_in[1];
    const float* w1  = (const float*)d_in[2];
    const float* w2  = (const float*)d_in[3];
    float* out = (float*)d_out;

    static int attr_done = 0;
    if (!attr_done) {
        cudaFuncSetAttribute(dist_approx, cudaFuncAttributeMaxDynamicSharedMemorySize,
                             DIST_SMEM);
        attr_done = 1;
    }

    k_init<<<64, 256>>>();
    fused_pre<<<dim3(4, 128, 2), 256>>>(z, emb, w1);
    gemm_cb<<<dim3(4, 128), 256>>>(w2);
    dist_approx<<<dim3(64, 128), 256, DIST_SMEM>>>();
    refine<<<2048, 256>>>();
    gather_loss<<<256, 256>>>(z, out);
    finalize<<<1, 256>>>(out);
}

// round 17
// speedup vs baseline: 1.8152x; 1.0415x over previous
#include <cuda_runtime.h>
#include <cuda_bf16.h>
#include <math.h>
#include <stdint.h>

// Problem constants (fixed by the dataset)
#define BB   2
#define DD   256
#define THW  8192
#define NN   16384
#define KK   8192

#define MARGIN 0.125f
#define CAP    1024

// -------- device scratch (no allocations allowed) --------
__device__ float g_CB[KK * DD];
__device__ __nv_bfloat16 g_CBhi[KK * DD];
__device__ __nv_bfloat16 g_Zhi[NN * DD];
__device__ __nv_bfloat16 g_Zlo[NN * DD];
__device__ __nv_bfloat16 g_Ehi[KK * DD];
__device__ __nv_bfloat16 g_Elo[KK * DD];
__device__ __nv_bfloat16 g_H1hi[KK * DD];
__device__ __nv_bfloat16 g_H1lo[KK * DD];
__device__ __nv_bfloat16 g_W1hi[DD * DD];
__device__ __nv_bfloat16 g_W1lo[DD * DD];
__device__ __nv_bfloat16 g_W2hi[DD * DD];
__device__ __nv_bfloat16 g_W2lo[DD * DD];
__device__ float g_cbsq[KK];
__device__ float g_csum[DD];
__device__ float g_zcol[DD];
__device__ float g_scal[3];
__device__ unsigned long long g_best[NN];
__device__ int   g_counts[KK];
__device__ int   g_ccount[NN];
__device__ unsigned short g_cand[(size_t)NN * CAP];   // 32 MB

// ================= PTX helpers (base sm_103-safe) =====
__device__ __forceinline__ uint32_t smem_to_u32(const void* p) {
    uint32_t a;
    asm("{ .reg .u64 t; cvta.to.shared.u64 t, %1; cvt.u32.u64 %0, t; }" : "=r"(a) : "l"(p));
    return a;
}
__device__ __forceinline__ void cpa16(uint32_t saddr, const void* g) {
    asm volatile("cp.async.cg.shared.global [%0], [%1], 16;" :: "r"(saddr), "l"(g) : "memory");
}
#define CP_COMMIT() asm volatile("cp.async.commit_group;" ::: "memory")
#define CP_WAIT1()  asm volatile("cp.async.wait_group 1;" ::: "memory")

__device__ __forceinline__ void ldsm4(uint32_t (&r)[4], uint32_t addr) {
    asm volatile("ldmatrix.sync.aligned.m8n8.x4.shared.b16 {%0,%1,%2,%3}, [%4];"
        : "=r"(r[0]), "=r"(r[1]), "=r"(r[2]), "=r"(r[3]) : "r"(addr));
}
__device__ __forceinline__ void mma16816(float (&d)[4], const uint32_t (&a)[4],
                                         uint32_t b0, uint32_t b1) {
    asm volatile("mma.sync.aligned.m16n8k16.row.col.f32.bf16.bf16.f32 "
        "{%0,%1,%2,%3}, {%4,%5,%6,%7}, {%8,%9}, {%0,%1,%2,%3};"
        : "+f"(d[0]), "+f"(d[1]), "+f"(d[2]), "+f"(d[3])
        : "r"(a[0]), "r"(a[1]), "r"(a[2]), "r"(a[3]), "r"(b0), "r"(b1));
}

// -------- helpers --------
__device__ __forceinline__ float blockReduceSum(float v) {
    __shared__ float sh[32];
    int lane = threadIdx.x & 31, w = threadIdx.x >> 5;
    #pragma unroll
    for (int o = 16; o; o >>= 1) v += __shfl_xor_sync(0xffffffffu, v, o);
    if (lane == 0) sh[w] = v;
    __syncthreads();
    v = (threadIdx.x < (blockDim.x >> 5)) ? sh[threadIdx.x] : 0.f;
    if (w == 0) {
        #pragma unroll
        for (int o = 16; o; o >>= 1) v += __shfl_xor_sync(0xffffffffu, v, o);
    }
    __syncthreads();
    return v;
}

__global__ void k_init() {
    int t = blockIdx.x * blockDim.x + threadIdx.x;
    if (t < NN) { g_best[t] = ~0ull; g_ccount[t] = 0; }
    if (t < KK) { g_counts[t] = 0; g_cbsq[t] = 0.f; }
    if (t < DD) { g_csum[t] = 0.f; g_zcol[t] = 0.f; }
    if (t < 3)  g_scal[t] = 0.f;
}

// -------- param split: emb/w1/w2 -> bf16 hi/lo --------
__global__ void __launch_bounds__(256) param_split(const float* __restrict__ emb,
                                                   const float* __restrict__ w1,
                                                   const float* __restrict__ w2) {
    int blk = blockIdx.x;
    const float* src;
    __nv_bfloat16 *dhi, *dlo;
    size_t base;
    if (blk < 1024) {
        src = emb; dhi = g_Ehi; dlo = g_Elo;
        base = ((size_t)blk * 256 + threadIdx.x) * 8;
    } else if (blk < 1056) {
        src = w1; dhi = g_W1hi; dlo = g_W1lo;
        base = ((size_t)(blk - 1024) * 256 + threadIdx.x) * 8;
    } else {
        src = w2; dhi = g_W2hi; dlo = g_W2lo;
        base = ((size_t)(blk - 1056) * 256 + threadIdx.x) * 8;
    }
    float4 a = *(const float4*)(src + base);
    float4 b = *(const float4*)(src + base + 4);
    float xs[8] = {a.x, a.y, a.z, a.w, b.x, b.y, b.z, b.w};
    uint32_t hw[4], lw[4];
    #pragma unroll
    for (int t = 0; t < 4; t++) {
        __nv_bfloat16 h0 = __float2bfloat16_rn(xs[2 * t]);
        __nv_bfloat16 h1 = __float2bfloat16_rn(xs[2 * t + 1]);
        __nv_bfloat162 hp = __halves2bfloat162(h0, h1);
        hw[t] = *reinterpret_cast<uint32_t*>(&hp);
        __nv_bfloat16 l0 = __float2bfloat16_rn(xs[2 * t] - __bfloat162float(h0));
        __nv_bfloat16 l1 = __float2bfloat16_rn(xs[2 * t + 1] - __bfloat162float(h1));
        __nv_bfloat162 lp = __halves2bfloat162(l0, l1);
        lw[t] = *reinterpret_cast<uint32_t*>(&lp);
    }
    *(uint4*)(dhi + base) = make_uint4(hw[0], hw[1], hw[2], hw[3]);
    *(uint4*)(dlo + base) = make_uint4(lw[0], lw[1], lw[2], lw[3]);
}

// -------- zsplit: transpose + bf16 split + stats --------
__global__ void __launch_bounds__(256) zsplit(const float* __restrict__ z) {
    __shared__ float sm[32][261];
    __shared__ float zc[32];
    int idx = blockIdx.x;
    int s0 = (idx & 31) * 256, d0 = ((idx >> 5) & 7) * 32, b = idx >> 8;
    int tid = threadIdx.x;
    if (tid < 32) zc[tid] = 0.f;
    const float* zp = z + ((size_t)b * 256 + d0) * THW + s0;
    #pragma unroll
    for (int i = 0; i < 32; i++) sm[i][tid] = zp[(size_t)i * THW + tid];
    __syncthreads();
    {
        int i = tid & 31, c = tid >> 5;
        float s = 0.f, s2 = 0.f;
        #pragma unroll
        for (int u = 0; u < 32; u++) {
            float v = sm[i][c * 32 + u];
            s += v; s2 += v * v;
        }
        atomicAdd(&zc[i], s);
        float ts2 = blockReduceSum(s2);
        if (tid == 0) atomicAdd(&g_scal[0], ts2);
    }
    int dseg = tid & 7, sl = tid >> 3;
    #pragma unroll
    for (int w = 0; w < 8; w++) {
        int s_i = w * 32 + sl;
        float x0 = sm[dseg * 4 + 0][s_i];
        float x1 = sm[dseg * 4 + 1][s_i];
        float x2 = sm[dseg * 4 + 2][s_i];
        float x3 = sm[dseg * 4 + 3][s_i];
        __nv_bfloat16 h0 = __float2bfloat16_rn(x0), h1 = __float2bfloat16_rn(x1);
        __nv_bfloat16 h2 = __float2bfloat16_rn(x2), h3 = __float2bfloat16_rn(x3);
        __nv_bfloat162 hp0 = __halves2bfloat162(h0, h1);
        __nv_bfloat162 hp1 = __halves2bfloat162(h2, h3);
        __nv_bfloat16 l0 = __float2bfloat16_rn(x0 - __bfloat162float(h0));
        __nv_bfloat16 l1 = __float2bfloat16_rn(x1 - __bfloat162float(h1));
        __nv_bfloat16 l2 = __float2bfloat16_rn(x2 - __bfloat162float(h2));
        __nv_bfloat16 l3 = __float2bfloat16_rn(x3 - __bfloat162float(h3));
        __nv_bfloat162 lp0 = __halves2bfloat162(l0, l1);
        __nv_bfloat162 lp1 = __halves2bfloat162(l2, l3);
        size_t base = ((size_t)(b * THW + s0 + s_i) * 256) + d0 + dseg * 4;
        *(uint2*)(g_Zhi + base) = make_uint2(*reinterpret_cast<uint32_t*>(&hp0),
                                             *reinterpret_cast<uint32_t*>(&hp1));
        *(uint2*)(g_Zlo + base) = make_uint2(*reinterpret_cast<uint32_t*>(&lp0),
                                             *reinterpret_cast<uint32_t*>(&lp1));
    }
    __syncthreads();
    if (tid < 32) atomicAdd(&g_zcol[d0 + tid], zc[tid]);
}

// ======== 3-term HMMA mainloop (R5-proven): acc = Ahi*Bhi + Alo*Bhi + Ahi*Blo
#define PRE_STAGE 32768
#define PRE_SMEM  (3 * 32768)
#define CB_SMEM   (3 * 32768 + 512)

__device__ __forceinline__ void issue3(uint32_t sbs,
                                       const __nv_bfloat16* Ah, const __nv_bfloat16* Al,
                                       const __nv_bfloat16* Bh, const __nv_bfloat16* Bl,
                                       int m0, int n0, int kc, int tid) {
    int row = tid >> 2, c = tid & 3;
    int k0 = kc * 32;
    #pragma unroll
    for (int half = 0; half < 2; half++) {
        int r = row + half * 64;
        uint32_t so = (uint32_t)(r * 64 + ((c ^ ((r >> 1) & 3)) << 4));
        size_t ga = (size_t)(m0 + r) * 256 + k0 + c * 8;
        size_t gb = (size_t)(n0 + r) * 256 + k0 + c * 8;
        cpa16(sbs + so,         Ah + ga);
        cpa16(sbs + 8192 + so,  Al + ga);
        cpa16(sbs + 16384 + so, Bh + gb);
        cpa16(sbs + 24576 + so, Bl + gb);
    }
    CP_COMMIT();
}

__device__ __forceinline__ void hmma3_body(uint32_t sb,
                                           const __nv_bfloat16* Ah, const __nv_bfloat16* Al,
                                           const __nv_bfloat16* Bh, const __nv_bfloat16* Bl,
                                           int m0, int n0, int tid,
                                           float (&acc)[2][8][4]) {
    int lane = tid & 31, wid = tid >> 5;
    int warp_m = wid >> 1, warp_n = wid & 1;
    int la7 = lane & 7, l3 = (lane >> 3) & 1, l4 = lane >> 4;
    uint32_t aoff[2]; int aswz[2];
    #pragma unroll
    for (int mi = 0; mi < 2; mi++) {
        int r = warp_m * 32 + mi * 16 + la7 + l3 * 8;
        aoff[mi] = (uint32_t)(r * 64);
        aswz[mi] = (r >> 1) & 3;
    }
    uint32_t boff[4]; int bswz[4];
    #pragma unroll
    for (int g = 0; g < 4; g++) {
        int r = warp_n * 64 + g * 16 + la7 + l4 * 8;
        boff[g] = (uint32_t)(16384 + r * 64);
        bswz[g] = (r >> 1) & 3;
    }
    #pragma unroll
    for (int mi = 0; mi < 2; mi++)
        #pragma unroll
        for (int nj = 0; nj < 8; nj++)
            #pragma unroll
            for (int q = 0; q < 4; q++) acc[mi][nj][q] = 0.f;

    issue3(sb, Ah, Al, Bh, Bl, m0, n0, 0, tid);
    issue3(sb + PRE_STAGE, Ah, Al, Bh, Bl, m0, n0, 1, tid);

    for (int kc = 0; kc < 8; kc++) {
        CP_WAIT1();
        __syncthreads();
        if (kc + 2 < 8)
            issue3(sb + ((kc + 2) % 3) * PRE_STAGE, Ah, Al, Bh, Bl, m0, n0, kc + 2, tid);
        uint32_t st = sb + (kc % 3) * PRE_STAGE;
        #pragma unroll
        for (int ki = 0; ki < 2; ki++) {
            uint32_t A0[2][4], A1[2][4], Bb[4][4];
            #pragma unroll
            for (int mi = 0; mi < 2; mi++) {
                uint32_t csel = (uint32_t)(((2 * ki + l4) ^ aswz[mi]) << 4);
                ldsm4(A0[mi], st + aoff[mi] + csel);
                ldsm4(A1[mi], st + 8192 + aoff[mi] + csel);
            }
            #pragma unroll
            for (int g = 0; g < 4; g++) {
                uint32_t csel = (uint32_t)(((2 * ki + l3) ^ bswz[g]) << 4);
                ldsm4(Bb[g], st + boff[g] + csel);
            }
            #pragma unroll
            for (int mi = 0; mi < 2; mi++)
                #pragma unroll
                for (int g = 0; g < 4; g++) {
                    mma16816(acc[mi][2 * g],     A0[mi], Bb[g][0], Bb[g][1]);
                    mma16816(acc[mi][2 * g + 1], A0[mi], Bb[g][2], Bb[g][3]);
                }
            #pragma unroll
            for (int mi = 0; mi < 2; mi++)
                #pragma unroll
                for (int g = 0; g < 4; g++) {
                    mma16816(acc[mi][2 * g],     A1[mi], Bb[g][0], Bb[g][1]);
                    mma16816(acc[mi][2 * g + 1], A1[mi], Bb[g][2], Bb[g][3]);
                }
            #pragma unroll
            for (int g = 0; g < 4; g++) {
                uint32_t csel = (uint32_t)(((2 * ki + l3) ^ bswz[g]) << 4);
                ldsm4(Bb[g], st + 8192 + boff[g] + csel);
            }
            #pragma unroll
            for (int mi = 0; mi < 2; mi++)
                #pragma unroll
                for (int g = 0; g < 4; g++) {
                    mma16816(acc[mi][2 * g],     A0[mi], Bb[g][0], Bb[g][1]);
                    mma16816(acc[mi][2 * g + 1], A0[mi], Bb[g][2], Bb[g][3]);
                }
        }
    }
}

// -------- gemm_h1: H1(hi/lo) = split(gelu(emb @ w1^T)) --------
__global__ void __launch_bounds__(256) gemm_h1() {
    extern __shared__ __align__(1024) char smem[];
    uint32_t sb = smem_to_u32(smem);
    int tid = threadIdx.x, lane = tid & 31, wid = tid >> 5;
    int warp_m = wid >> 1, warp_n = wid & 1;
    int m0 = blockIdx.y * 128, n0 = blockIdx.x * 128;
    float acc[2][8][4];
    hmma3_body(sb, g_Ehi, g_Elo, g_W1hi, g_W1lo, m0, n0, tid, acc);

    #pragma unroll
    for (int mi = 0; mi < 2; mi++)
        #pragma unroll
        for (int h = 0; h < 2; h++) {
            int r = warp_m * 32 + mi * 16 + (lane >> 2) + h * 8;
            size_t rowb = (size_t)(m0 + r) * 256 + n0;
            #pragma unroll
            for (int nj = 0; nj < 8; nj++) {
                int c0 = warp_n * 64 + nj * 8 + (lane & 3) * 2;
                float v0 = acc[mi][nj][h * 2];
                float v1 = acc[mi][nj][h * 2 + 1];
                float x0 = 0.5f * v0 * (1.f + erff(v0 * 0.70710678118654752f));
                float x1 = 0.5f * v1 * (1.f + erff(v1 * 0.70710678118654752f));
                __nv_bfloat16 h0 = __float2bfloat16_rn(x0);
                __nv_bfloat16 h1 = __float2bfloat16_rn(x1);
                __nv_bfloat162 hp = __halves2bfloat162(h0, h1);
                __nv_bfloat16 l0 = __float2bfloat16_rn(x0 - __bfloat162float(h0));
                __nv_bfloat16 l1 = __float2bfloat16_rn(x1 - __bfloat162float(h1));
                __nv_bfloat162 lp = __halves2bfloat162(l0, l1);
                *(uint32_t*)(g_H1hi + rowb + c0) = *reinterpret_cast<uint32_t*>(&hp);
                *(uint32_t*)(g_H1lo + rowb + c0) = *reinterpret_cast<uint32_t*>(&lp);
            }
        }
}

// -------- gemm_cb2: CB = H1 @ w2^T + stats/CBhi epilogue --------
__global__ void __launch_bounds__(256) gemm_cb2() {
    extern __shared__ __align__(1024) char smem[];
    uint32_t sb = smem_to_u32(smem);
    float* colsum = (float*)(smem + PRE_SMEM);
    int tid = threadIdx.x, lane = tid & 31, wid = tid >> 5;
    int warp_m = wid >> 1, warp_n = wid & 1;
    int m0 = blockIdx.y * 128, n0 = blockIdx.x * 128;
    if (tid < 128) colsum[tid] = 0.f;
    float acc[2][8][4];
    hmma3_body(sb, g_H1hi, g_H1lo, g_W2hi, g_W2lo, m0, n0, tid, acc);

    float sqtot = 0.f;
    #pragma unroll
    for (int mi = 0; mi < 2; mi++)
        #pragma unroll
        for (int h = 0; h < 2; h++) {
            int r = warp_m * 32 + mi * 16 + (lane >> 2) + h * 8;
            size_t rowb = (size_t)(m0 + r) * 256 + n0;
            float rsq = 0.f;
            #pragma unroll
            for (int nj = 0; nj < 8; nj++) {
                int lc = warp_n * 64 + nj * 8 + (lane & 3) * 2;
                float v0 = acc[mi][nj][h * 2];
                float v1 = acc[mi][nj][h * 2 + 1];
                *(float2*)(g_CB + rowb + lc) = make_float2(v0, v1);
                __nv_bfloat16 h0 = __float2bfloat16_rn(v0);
                __nv_bfloat16 h1 = __float2bfloat16_rn(v1);
                __nv_bfloat162 hp = __halves2bfloat162(h0, h1);
                *(uint32_t*)(g_CBhi + rowb + lc) = *reinterpret_cast<uint32_t*>(&hp);
                rsq += v0 * v0 + v1 * v1;
                atomicAdd(&colsum[lc], v0);
                atomicAdd(&colsum[lc + 1], v1);
            }
            sqtot += rsq;
            float rr = rsq;
            rr += __shfl_xor_sync(0xffffffffu, rr, 1);
            rr += __shfl_xor_sync(0xffffffffu, rr, 2);
            if ((lane & 3) == 0) atomicAdd(&g_cbsq[m0 + r], rr);
        }
    float bs = blockReduceSum(sqtot);
    if (tid == 0) atomicAdd(&g_scal[1], bs);
    __syncthreads();
    if (tid < 128) atomicAdd(&g_csum[n0 + tid], colsum[tid]);
}

// ======== approx HMMA distance (hi*hi only) + candidate push (R7 proven) ====
#define STAGE_BYTES 16384
#define SM_CBSQ     (3 * STAGE_BYTES)
#define SM_BEST     (SM_CBSQ + 512)
#define SM_THRESH   (SM_BEST + 1024)
#define DIST_SMEM   (SM_THRESH + 512)

__device__ __forceinline__ void issue_chunk(uint32_t sb_stage, int m0, int n0,
                                            int kc, int tid) {
    int row = tid >> 2, c = tid & 3;
    int k0 = kc * 32;
    #pragma unroll
    for (int half = 0; half < 2; half++) {
        int r = row + half * 64;
        uint32_t so = (uint32_t)(r * 64 + ((c ^ ((r >> 1) & 3)) << 4));
        cpa16(sb_stage + so,        g_Zhi + (size_t)(m0 + r) * 256 + k0 + c * 8);
        cpa16(sb_stage + 8192 + so, g_CBhi + (size_t)(n0 + r) * 256 + k0 + c * 8);
    }
    CP_COMMIT();
}

__global__ void __launch_bounds__(256, 2) dist_approx() {
    extern __shared__ __align__(1024) char smem[];
    uint32_t sb = smem_to_u32(smem);
    float* cbsq_s = (float*)(smem + SM_CBSQ);
    unsigned long long* bestsh = (unsigned long long*)(smem + SM_BEST);
    float* threshsh = (float*)(smem + SM_THRESH);

    int tid = threadIdx.x, lane = tid & 31, wid = tid >> 5;
    int warp_m = wid >> 1, warp_n = wid & 1;
    int m0 = blockIdx.y * 128, n0 = blockIdx.x * 128;

    if (tid < 128) { cbsq_s[tid] = g_cbsq[n0 + tid]; bestsh[tid] = ~0ull; }

    int la7 = lane & 7, l3 = (lane >> 3) & 1, l4 = lane >> 4;
    uint32_t aoff[2]; int aswz[2];
    #pragma unroll
    for (int mi = 0; mi < 2; mi++) {
        int r = warp_m * 32 + mi * 16 + la7 + l3 * 8;
        aoff[mi] = (uint32_t)(r * 64);
        aswz[mi] = (r >> 1) & 3;
    }
    uint32_t boff[4]; int bswz[4];
    #pragma unroll
    for (int g = 0; g < 4; g++) {
        int r = warp_n * 64 + g * 16 + la7 + l4 * 8;
        boff[g] = (uint32_t)(8192 + r * 64);
        bswz[g] = (r >> 1) & 3;
    }

    float acc[2][8][4];
    #pragma unroll
    for (int mi = 0; mi < 2; mi++)
        #pragma unroll
        for (int nj = 0; nj < 8; nj++)
            #pragma unroll
            for (int q = 0; q < 4; q++) acc[mi][nj][q] = 0.f;

    issue_chunk(sb, m0, n0, 0, tid);
    issue_chunk(sb + STAGE_BYTES, m0, n0, 1, tid);

    for (int kc = 0; kc < 8; kc++) {
        CP_WAIT1();
        __syncthreads();
        if (kc + 2 < 8)
            issue_chunk(sb + ((kc + 2) % 3) * STAGE_BYTES, m0, n0, kc + 2, tid);
        uint32_t st = sb + (kc % 3) * STAGE_BYTES;
        #pragma unroll
        for (int ki = 0; ki < 2; ki++) {
            uint32_t A0[2][4], Bb[4][4];
            #pragma unroll
            for (int mi = 0; mi < 2; mi++) {
                uint32_t csel = (uint32_t)(((2 * ki + l4) ^ aswz[mi]) << 4);
                ldsm4(A0[mi], st + aoff[mi] + csel);
            }
            #pragma unroll
            for (int g = 0; g < 4; g++) {
                uint32_t csel = (uint32_t)(((2 * ki + l3) ^ bswz[g]) << 4);
                ldsm4(Bb[g], st + boff[g] + csel);
            }
            #pragma unroll
            for (int mi = 0; mi < 2; mi++)
                #pragma unroll
                for (int g = 0; g < 4; g++) {
                    mma16816(acc[mi][2 * g],     A0[mi], Bb[g][0], Bb[g][1]);
                    mma16816(acc[mi][2 * g + 1], A0[mi], Bb[g][2], Bb[g][3]);
                }
        }
    }

    // ---- pass 1: local argmin, quad reduce, atomicMin ----
    float bestvt[4];
    #pragma unroll
    for (int mi = 0; mi < 2; mi++)
        #pragma unroll
        for (int h = 0; h < 2; h++) {
            int rloc = warp_m * 32 + mi * 16 + (lane >> 2) + h * 8;
            float bestv = 3.4e38f;
            int besti = 0;
            #pragma unroll
            for (int nj = 0; nj < 8; nj++)
                #pragma unroll
                for (int e = 0; e < 2; e++) {
                    int col = warp_n * 64 + nj * 8 + (lane & 3) * 2 + e;
                    float sc = fmaf(-2.f, acc[mi][nj][h * 2 + e], cbsq_s[col]);
                    if (sc < bestv) { bestv = sc; besti = n0 + col; }
                }
            bestvt[mi * 2 + h] = bestv;
            uint32_t fb = __float_as_uint(bestv);
            uint32_t key = (fb & 0x80000000u) ? ~fb : (fb | 0x80000000u);
            unsigned long long best =
                ((unsigned long long)key << 32) | (unsigned)besti;
            unsigned long long o1 = __shfl_xor_sync(0xffffffffu, best, 1);
            best = best < o1 ? best : o1;
            unsigned long long o2 = __shfl_xor_sync(0xffffffffu, best, 2);
            best = best < o2 ? best : o2;
            if ((lane & 3) == 0) atomicMin(&bestsh[rloc], best);
        }
    __syncthreads();
    if (tid < 128) {
        unsigned long long mine = bestsh[tid];
        unsigned long long old = atomicMin(&g_best[m0 + tid], mine);
        unsigned long long merged = old < mine ? old : mine;
        uint32_t key = (uint32_t)(merged >> 32);
        uint32_t fb = (key & 0x80000000u) ? (key & 0x7fffffffu) : ~key;
        threshsh[tid] = __uint_as_float(fb) + MARGIN;
    }
    __syncthreads();

    // ---- pass 2: push candidates (skip-guarded by pass-1 per-thread min) ----
    #pragma unroll
    for (int mi = 0; mi < 2; mi++)
        #pragma unroll
        for (int h = 0; h < 2; h++) {
            int rloc = warp_m * 32 + mi * 16 + (lane >> 2) + h * 8;
            float th = threshsh[rloc];
            if (bestvt[mi * 2 + h] > th) continue;
            int token = m0 + rloc;
            #pragma unroll
            for (int nj = 0; nj < 8; nj++)
                #pragma unroll
                for (int e = 0; e < 2; e++) {
                    int col = warp_n * 64 + nj * 8 + (lane & 3) * 2 + e;
                    float sc = fmaf(-2.f, acc[mi][nj][h * 2 + e], cbsq_s[col]);
                    if (sc <= th) {
                        int ix = atomicAdd(&g_ccount[token], 1);
                        if (ix < CAP)
                            g_cand[(size_t)token * CAP + ix] =
                                (unsigned short)(n0 + col);
                    }
                }
        }
}

// ======== refine: exact fp32 re-score of pushed candidates ========
__global__ void __launch_bounds__(256) refine() {
    int wid = threadIdx.x >> 5, lane = threadIdx.x & 31;
    int n = blockIdx.x * 8 + wid;
    int cnt = g_ccount[n];
    if (cnt > CAP) cnt = CAP;

    uint4 vh = *(const uint4*)(g_Zhi + (size_t)n * 256 + lane * 8);
    uint4 vl = *(const uint4*)(g_Zlo + (size_t)n * 256 + lane * 8);
    float zf[8];
    {
        const __nv_bfloat162* hp = (const __nv_bfloat162*)&vh;
        const __nv_bfloat162* lp = (const __nv_bfloat162*)&vl;
        #pragma unroll
        for (int t = 0; t < 4; t++) {
            float2 fh = __bfloat1622float2(hp[t]);
            float2 fl = __bfloat1622float2(lp[t]);
            zf[2 * t] = fh.x + fl.x;
            zf[2 * t + 1] = fh.y + fl.y;
        }
    }

    unsigned long long best = ~0ull;
    const unsigned short* cl = g_cand + (size_t)n * CAP;
    for (int c = 0; c < cnt; c++) {
        int code = cl[c];
        const float4* cb = (const float4*)(g_CB + (size_t)code * 256 + lane * 8);
        float4 c0 = cb[0], c1 = cb[1];
        float d = zf[0] * c0.x + zf[1] * c0.y + zf[2] * c0.z + zf[3] * c0.w
                + zf[4] * c1.x + zf[5] * c1.y + zf[6] * c1.z + zf[7] * c1.w;
        #pragma unroll
        for (int o = 16; o; o >>= 1) d += __shfl_xor_sync(0xffffffffu, d, o);
        float sc = fmaf(-2.f, d, g_cbsq[code]);
        uint32_t fb = __float_as_uint(sc);
        uint32_t key = (fb & 0x80000000u) ? ~fb : (fb | 0x80000000u);
        unsigned long long u = ((unsigned long long)key << 32) | (unsigned)code;
        best = best < u ? best : u;
    }
    if (lane == 0) g_best[n] = best;
}

// -------- gather z_q + loss + histogram (coalesced CB rows) --------
__global__ void __launch_bounds__(256) gather_loss(const float* __restrict__ z,
                                                   float* __restrict__ out) {
    int x = blockIdx.x;
    int b = x >> 7, s0 = (x & 127) * 64;
    int t = threadIdx.x;
    int s = s0 + (t & 63);
    int d4b = t >> 6;
    int n = b * THW + s;
    int id = (int)(unsigned int)(g_best[n] & 0xffffffffull);
    if (t < 64) atomicAdd(&g_counts[id], 1);
    const float* cbrow = g_CB + (size_t)id * 256;
    size_t ebase = ((size_t)b << 21) + s;
    float lsum = 0.f;
    #pragma unroll 4
    for (int it = 0; it < 16; it++) {
        int d4 = d4b + 4 * it;
        float4 q = *(const float4*)(cbrow + d4 * 4);
        size_t e = ebase + (size_t)(d4 * 4) * THW;
        float z0 = z[e];            out[e] = q.x;
        float z1 = z[e + THW];      out[e + THW] = q.y;
        float z2 = z[e + 2 * THW];  out[e + 2 * THW] = q.z;
        float z3 = z[e + 3 * THW];  out[e + 3 * THW] = q.w;
        float d0 = q.x - z0, d1 = q.y - z1, d2 = q.z - z2, d3 = q.w - z3;
        lsum += d0 * d0 + d1 * d1 + d2 * d2 + d3 * d3;
    }
    float ls = blockReduceSum(lsum);
    if (t == 0) atomicAdd(&g_scal[2], ls);
}

// -------- finalize scalars --------
__global__ void __launch_bounds__(256) finalize(float* __restrict__ out) {
    float ps = 0.f;
    for (int k = threadIdx.x; k < KK; k += 256) {
        float e = (float)g_counts[k] * (1.f / (float)NN);
        ps += e * logf(e + 1e-10f);
    }
    float ent = blockReduceSum(ps);
    float dp = (g_zcol[threadIdx.x] * (1.f / (float)NN)) *
               (g_csum[threadIdx.x] * (1.f / (float)KK));
    float dot = blockReduceSum(dp);
    if (threadIdx.x == 0) {
        float loss = 1.25f * g_scal[2] / (float)((size_t)NN * DD);
        float perp = expf(-ent);
        float meand = g_scal[0] / (float)NN + g_scal[1] / (float)KK - 2.f * dot;
        out[4194304] = loss;
        out[4194305] = perp;
        out[4194306] = meand;
    }
}

extern "C" void kernel_launch(void* const* d_in, const int* in_sizes, int n_in,
                              void* d_out, int out_size) {
    const float* z   = (const float*)d_in[0];
    const float* emb = (const float*)d_in[1];
    const float* w1  = (const float*)d_in[2];
    const float* w2  = (const float*)d_in[3];
    float* out = (float*)d_out;

    static int attr_done = 0;
    if (!attr_done) {
        cudaFuncSetAttribute(dist_approx, cudaFuncAttributeMaxDynamicSharedMemorySize,
                             DIST_SMEM);
        cudaFuncSetAttribute(gemm_h1, cudaFuncAttributeMaxDynamicSharedMemorySize,
                             PRE_SMEM);
        cudaFuncSetAttribute(gemm_cb2, cudaFuncAttributeMaxDynamicSharedMemorySize,
                             CB_SMEM);
        attr_done = 1;
    }

    k_init<<<64, 256>>>();
    param_split<<<1088, 256>>>(emb, w1, w2);
    zsplit<<<512, 256>>>(z);
    gemm_h1<<<dim3(2, 64), 256, PRE_SMEM>>>();
    gemm_cb2<<<dim3(2, 64), 256, CB_SMEM>>>();
    dist_approx<<<dim3(64, 128), 256, DIST_SMEM>>>();
    refine<<<2048, 256>>>();
    gather_loss<<<256, 256>>>(z, out);
    finalize<<<1, 256>>>(out);
}